// round 16
// baseline (speedup 1.0000x reference)
#include <cuda_runtime.h>
#include <math.h>

#define VSZ 8192
#define DSZ 128
#define NH 8
#define HDIM 16
#define NL 2
#define SQ 128
#define HID 341
#define KP2 352
#define EPSV 1e-6f
#define NBLK 48

// Scratch (device globals: allocation-free)
__device__ float g_x[SQ*DSZ];
__device__ float g_q[SQ*DSZ];
__device__ float g_k[SQ*DSZ];
__device__ float g_v[SQ*DSZ];
__device__ float g_g[SQ*HID];
__device__ float g_xnT[DSZ*SQ];   // final normalized tokens, transposed [d][s]

// Software grid barrier state (sense-reversing; self-resetting across replays)
__device__ unsigned g_bar_count = 0;
__device__ unsigned g_bar_gen = 0;

__device__ __forceinline__ void grid_sync() {
    __syncthreads();
    if (threadIdx.x == 0) {
        __threadfence();
        unsigned gen = *(volatile unsigned*)&g_bar_gen;
        unsigned arrived = atomicAdd(&g_bar_count, 1u);
        if (arrived == NBLK - 1u) {
            atomicExch(&g_bar_count, 0u);
            __threadfence();
            atomicAdd(&g_bar_gen, 1u);
        } else {
            while (*(volatile unsigned*)&g_bar_gen == gen) { __nanosleep(32); }
        }
        __threadfence();
    }
    __syncthreads();
}

__device__ __forceinline__ float sigmoidf_(float x) { return 1.0f/(1.0f + __expf(-x)); }

// =====================================================================
// Fused transformer, 4 grid barriers total.
// grid NBLK=48 x 256 threads. block b: rt=b&7 (16-row tile), u=b>>3 (0..5).
// =====================================================================
__global__ __launch_bounds__(256) void fused_kernel(
    const int* __restrict__ idx,
    const float* __restrict__ w_raw,
    const float* __restrict__ n1w,
    const float* __restrict__ n2w,
    const float* __restrict__ wq,
    const float* __restrict__ wk,
    const float* __restrict__ wv,
    const float* __restrict__ wo,
    const float* __restrict__ w1,
    const float* __restrict__ w3,
    const float* __restrict__ w2,
    const float* __restrict__ fw)
{
    __shared__ __align__(16) float smem_f[12288];  // 48KB, per-phase unions
    const int t = threadIdx.x;
    const int b = blockIdx.x;
    const int rt = b & 7;
    const int row0 = rt * 16;
    const int u = b >> 3;            // 0..5 : mat=u>>1 (q/k/v), colhalf=u&1
    const int mat = u >> 1;
    const int col0 = (u & 1) * 64;

    // ================= PHASE A: embed + rms1 + qkv(layer 0) =================
    {
        float (*xs)[128] = (float(*)[128])smem_f;
        float (*ws)[64]  = (float(*)[64])(smem_f + 2048);
        float (*ps)[16]  = (float(*)[16])(smem_f + 4096);
        float *rs        = smem_f + 4352;

        for (int e = t; e < 2048; e += 256) {
            int s = row0 + (e>>7), d = e & 127;
            xs[e>>7][d] = sigmoidf_(w_raw[d*VSZ + idx[s]]);
        }
        __syncthreads();
        if (u == 0)
            for (int e = t; e < 2048; e += 256)
                g_x[(row0 + (e>>7))*DSZ + (e&127)] = xs[e>>7][e&127];
        {
            int r = t>>4, i = t&15;
            float sum = 0.0f;
            #pragma unroll
            for (int j = 0; j < 8; j++) { float vv = xs[r][i*8+j]; sum += vv*vv; }
            ps[r][i] = sum;
        }
        __syncthreads();
        if (t < 16) {
            float sum = 0.0f;
            #pragma unroll
            for (int i = 0; i < 16; i++) sum += ps[t][i];
            rs[t] = rsqrtf(sum * (1.0f/128.0f) + EPSV);
        }
        __syncthreads();
        {
            int r = t>>4, i = t&15;
            float sc = rs[r];
            const float* nw = n1w;  // layer 0
            #pragma unroll
            for (int j = 0; j < 8; j++) { int c = i*8+j; xs[r][c] = xs[r][c]*sc*nw[c]; }
        }
        __syncthreads();

        const float* W = (mat==0 ? wq : (mat==1 ? wk : wv));  // layer 0
        int r = t>>4, c4 = (t&15)*4;
        float acc[4] = {0,0,0,0};
        for (int kt = 0; kt < 128; kt += 32) {
            for (int f = t; f < 512; f += 256) {
                int kk = f>>4, cc = (f&15)*4;
                *(float4*)&ws[kk][cc] = *(const float4*)&W[(kt+kk)*DSZ + col0 + cc];
            }
            __syncthreads();
            #pragma unroll
            for (int kk = 0; kk < 32; kk++) {
                float a = xs[r][kt+kk];
                float4 w0 = *(float4*)&ws[kk][c4];
                acc[0] += a*w0.x; acc[1] += a*w0.y; acc[2] += a*w0.z; acc[3] += a*w0.w;
            }
            __syncthreads();
        }
        int i = row0 + r;
        float* out = (mat==0 ? g_q : (mat==1 ? g_k : g_v));
        int cg = col0 + c4;
        if (mat < 2) {
            #pragma unroll
            for (int p = 0; p < 2; p++) {
                int c = cg + 2*p;
                int jj = (c & 15) >> 1;
                float inv = __powf(10000.0f, -(float)jj * 0.125f);
                float ang = (float)i * inv;
                float sn_, cs_;
                __sincosf(ang, &sn_, &cs_);
                float x0 = acc[2*p], x1 = acc[2*p+1];
                acc[2*p]   = x0*cs_ - x1*sn_;
                acc[2*p+1] = x0*sn_ + x1*cs_;
            }
        }
        #pragma unroll
        for (int j = 0; j < 4; j++) out[i*DSZ + cg + j] = acc[j];
    }
    grid_sync();   // barrier 1

    for (int layer = 0; layer < NL; layer++) {
        // ============ PHASE B: attn(all heads) + wo + resid + rms2 + ffn1 ============
        {
            // --- attention: 2 subunits x 4 iterations cover 8 heads, rows row0..row0+15
            int sub = t >> 7, tt = t & 127;
            float (*ks)[17] = (float(*)[17])(smem_f + sub*4352);
            float (*vs)[17] = (float(*)[17])(smem_f + sub*4352 + 2176);
            float (*ao)[128] = (float(*)[128])(smem_f + 8704);
            int tq = tt >> 3, tk = tt & 7;
            int i = row0 + tq;
            for (int hh = 0; hh < 4; hh++) {
                int h = hh*2 + sub;
                for (int e = tt; e < 2048; e += 128) {
                    int j = e>>4, c = e&15;
                    ks[j][c] = g_k[j*DSZ + h*HDIM + c];
                    vs[j][c] = g_v[j*DSZ + h*HDIM + c];
                }
                __syncthreads();
                float4 q0, q1, q2, q3;
                {
                    const float4* qp = (const float4*)(g_q + i*DSZ + h*HDIM);
                    q0 = qp[0]; q1 = qp[1]; q2 = qp[2]; q3 = qp[3];
                }
                float s[16];
                float mloc = -1e30f;
                #pragma unroll
                for (int n = 0; n < 16; n++) {
                    int j = tk + n*8;
                    float sv = -1e30f;
                    if (j <= i) {
                        float d = q0.x*ks[j][0] + q0.y*ks[j][1] + q0.z*ks[j][2] + q0.w*ks[j][3]
                                + q1.x*ks[j][4] + q1.y*ks[j][5] + q1.z*ks[j][6] + q1.w*ks[j][7]
                                + q2.x*ks[j][8] + q2.y*ks[j][9] + q2.z*ks[j][10]+ q2.w*ks[j][11]
                                + q3.x*ks[j][12]+ q3.y*ks[j][13]+ q3.z*ks[j][14]+ q3.w*ks[j][15];
                        sv = d * 0.25f;
                    }
                    s[n] = sv;
                    mloc = fmaxf(mloc, sv);
                }
                mloc = fmaxf(mloc, __shfl_xor_sync(0xFFFFFFFFu, mloc, 1));
                mloc = fmaxf(mloc, __shfl_xor_sync(0xFFFFFFFFu, mloc, 2));
                mloc = fmaxf(mloc, __shfl_xor_sync(0xFFFFFFFFu, mloc, 4));
                float lsum = 0.0f;
                #pragma unroll
                for (int n = 0; n < 16; n++) {
                    int j = tk + n*8;
                    float pv = 0.0f;
                    if (j <= i) pv = __expf(s[n] - mloc);
                    s[n] = pv;
                    lsum += pv;
                }
                lsum += __shfl_xor_sync(0xFFFFFFFFu, lsum, 1);
                lsum += __shfl_xor_sync(0xFFFFFFFFu, lsum, 2);
                lsum += __shfl_xor_sync(0xFFFFFFFFu, lsum, 4);
                float o16[16];
                #pragma unroll
                for (int c = 0; c < 16; c++) o16[c] = 0.0f;
                #pragma unroll
                for (int n = 0; n < 16; n++) {
                    int j = tk + n*8;
                    if (j <= i) {
                        float pv = s[n];
                        #pragma unroll
                        for (int c = 0; c < 16; c++) o16[c] += pv*vs[j][c];
                    }
                }
                #pragma unroll
                for (int c = 0; c < 16; c++) {
                    float v = o16[c];
                    v += __shfl_xor_sync(0xFFFFFFFFu, v, 1);
                    v += __shfl_xor_sync(0xFFFFFFFFu, v, 2);
                    v += __shfl_xor_sync(0xFFFFFFFFu, v, 4);
                    o16[c] = v;
                }
                float invl = 1.0f / lsum;
                ao[tq][h*HDIM + 2*tk    ] = o16[2*tk]   * invl;
                ao[tq][h*HDIM + 2*tk + 1] = o16[2*tk+1] * invl;
                __syncthreads();
            }

            // --- wo (full 128 cols) + residual
            float (*xs)[128]  = (float(*)[128])smem_f;
            float (*ws2)[128] = (float(*)[128])(smem_f + 2048);
            for (int e = t; e < 2048; e += 256)
                xs[e>>7][e&127] = g_x[(row0 + (e>>7))*DSZ + (e&127)];
            __syncthreads();
            const float* W = wo + layer*DSZ*DSZ;
            int r = t>>4, c8 = (t&15)*8;
            float acc[8];
            #pragma unroll
            for (int j = 0; j < 8; j++) acc[j] = 0.0f;
            for (int kt = 0; kt < 128; kt += 32) {
                for (int f = t; f < 1024; f += 256) {
                    int kk = f>>5, cc = (f&31)*4;
                    *(float4*)&ws2[kk][cc] = *(const float4*)&W[(kt+kk)*DSZ + cc];
                }
                __syncthreads();
                #pragma unroll
                for (int kk = 0; kk < 32; kk++) {
                    float a = ao[r][kt+kk];
                    float4 w0 = *(float4*)&ws2[kk][c8];
                    float4 w1 = *(float4*)&ws2[kk][c8+4];
                    acc[0] += a*w0.x; acc[1] += a*w0.y; acc[2] += a*w0.z; acc[3] += a*w0.w;
                    acc[4] += a*w1.x; acc[5] += a*w1.y; acc[6] += a*w1.z; acc[7] += a*w1.w;
                }
                __syncthreads();
            }
            #pragma unroll
            for (int j = 0; j < 8; j++) xs[r][c8+j] += acc[j];
            __syncthreads();
            if (u == 0)
                for (int e = t; e < 2048; e += 256)
                    g_x[(row0 + (e>>7))*DSZ + (e&127)] = xs[e>>7][e&127];

            // --- rms2 (in place)
            float (*ps)[16] = (float(*)[16])(smem_f + 2048);
            float *rs       = smem_f + 2304;
            {
                int rr = t>>4, ii = t&15;
                float sum = 0.0f;
                #pragma unroll
                for (int j = 0; j < 8; j++) { float vv = xs[rr][ii*8+j]; sum += vv*vv; }
                ps[rr][ii] = sum;
            }
            __syncthreads();
            if (t < 16) {
                float sum = 0.0f;
                #pragma unroll
                for (int i2 = 0; i2 < 16; i2++) sum += ps[t][i2];
                rs[t] = rsqrtf(sum * (1.0f/128.0f) + EPSV);
            }
            __syncthreads();
            {
                int rr = t>>4, ii = t&15;
                float sc = rs[rr];
                const float* nw = n2w + layer*DSZ;
                #pragma unroll
                for (int j = 0; j < 8; j++) { int c = ii*8+j; xs[rr][c] = xs[rr][c]*sc*nw[c]; }
            }
            __syncthreads();

            // --- ffn1 slice (u = ct, 64 HID cols)
            float (*w1s)[64] = (float(*)[64])(smem_f + 2560);
            float (*w3s)[64] = (float(*)[64])(smem_f + 4608);
            const float* W1 = w1 + layer*DSZ*HID;
            const float* W3 = w3 + layer*DSZ*HID;
            int cl0 = (t&15)*4;
            float a1[4] = {0,0,0,0}, a3[4] = {0,0,0,0};
            for (int kt = 0; kt < 128; kt += 32) {
                for (int f = t; f < 2048; f += 256) {
                    int kk = f>>6, cc = f&63;
                    int c = u*64 + cc;
                    float v1 = 0.0f, v3 = 0.0f;
                    if (c < HID) { v1 = W1[(kt+kk)*HID + c]; v3 = W3[(kt+kk)*HID + c]; }
                    w1s[kk][cc] = v1; w3s[kk][cc] = v3;
                }
                __syncthreads();
                #pragma unroll
                for (int kk = 0; kk < 32; kk++) {
                    float a = xs[r][kt+kk];
                    float4 u1 = *(float4*)&w1s[kk][cl0];
                    float4 u3 = *(float4*)&w3s[kk][cl0];
                    a1[0] += a*u1.x; a1[1] += a*u1.y; a1[2] += a*u1.z; a1[3] += a*u1.w;
                    a3[0] += a*u3.x; a3[1] += a*u3.y; a3[2] += a*u3.z; a3[3] += a*u3.w;
                }
                __syncthreads();
            }
            #pragma unroll
            for (int j = 0; j < 4; j++) {
                int c = u*64 + cl0 + j;
                if (c < HID) {
                    float s1 = a1[j];
                    g_g[(row0+r)*HID + c] = (s1 / (1.0f + __expf(-s1))) * a3[j];
                }
            }
        }
        grid_sync();   // barrier 2 / 4

        // ============ PHASE C: ffn2(full) + resid, then qkv(next) or finalnorm ============
        {
            float (*gs)[KP2]  = (float(*)[KP2])smem_f;            // 5632
            float (*xs)[128]  = (float(*)[128])(smem_f + 5632);   // 2048
            float (*ws2)[128] = (float(*)[128])(smem_f + 7680);   // 4096
            for (int e = t; e < 16*KP2; e += 256) {
                int rr = e / KP2, c = e % KP2;
                gs[rr][c] = (c < HID) ? g_g[(row0 + rr)*HID + c] : 0.0f;
            }
            for (int e = t; e < 2048; e += 256)
                xs[e>>7][e&127] = g_x[(row0 + (e>>7))*DSZ + (e&127)];
            __syncthreads();
            const float* W = w2 + layer*HID*DSZ;
            int r = t>>4, c8 = (t&15)*8;
            float acc[8];
            #pragma unroll
            for (int j = 0; j < 8; j++) acc[j] = 0.0f;
            for (int kt = 0; kt < KP2; kt += 32) {
                for (int f = t; f < 1024; f += 256) {
                    int kk = f>>5, cc = (f&31)*4;
                    int row = kt + kk;
                    float4 v = make_float4(0.f,0.f,0.f,0.f);
                    if (row < HID) v = *(const float4*)&W[row*DSZ + cc];
                    *(float4*)&ws2[kk][cc] = v;
                }
                __syncthreads();
                #pragma unroll
                for (int kk = 0; kk < 32; kk++) {
                    float a = gs[r][kt+kk];
                    float4 w0 = *(float4*)&ws2[kk][c8];
                    float4 w1 = *(float4*)&ws2[kk][c8+4];
                    acc[0] += a*w0.x; acc[1] += a*w0.y; acc[2] += a*w0.z; acc[3] += a*w0.w;
                    acc[4] += a*w1.x; acc[5] += a*w1.y; acc[6] += a*w1.z; acc[7] += a*w1.w;
                }
                __syncthreads();
            }
            #pragma unroll
            for (int j = 0; j < 8; j++) xs[r][c8+j] += acc[j];
            __syncthreads();

            if (layer < NL-1) {
                if (u == 0)
                    for (int e = t; e < 2048; e += 256)
                        g_x[(row0 + (e>>7))*DSZ + (e&127)] = xs[e>>7][e&127];
                // rms1(layer+1)
                float (*ps)[16] = (float(*)[16])(smem_f + 11776);
                float *rs       = smem_f + 12032;
                {
                    int rr = t>>4, ii = t&15;
                    float sum = 0.0f;
                    #pragma unroll
                    for (int j = 0; j < 8; j++) { float vv = xs[rr][ii*8+j]; sum += vv*vv; }
                    ps[rr][ii] = sum;
                }
                __syncthreads();
                if (t < 16) {
                    float sum = 0.0f;
                    #pragma unroll
                    for (int i2 = 0; i2 < 16; i2++) sum += ps[t][i2];
                    rs[t] = rsqrtf(sum * (1.0f/128.0f) + EPSV);
                }
                __syncthreads();
                {
                    int rr = t>>4, ii = t&15;
                    float sc = rs[rr];
                    const float* nw = n1w + (layer+1)*DSZ;
                    #pragma unroll
                    for (int j = 0; j < 8; j++) { int c = ii*8+j; xs[rr][c] = xs[rr][c]*sc*nw[c]; }
                }
                __syncthreads();
                // qkv(layer+1), slice u
                float (*ws)[64] = (float(*)[64])(smem_f + 7680);
                const float* Wn = (mat==0 ? wq : (mat==1 ? wk : wv)) + (layer+1)*DSZ*DSZ;
                int c4 = (t&15)*4;
                float qacc[4] = {0,0,0,0};
                for (int kt = 0; kt < 128; kt += 32) {
                    for (int f = t; f < 512; f += 256) {
                        int kk = f>>4, cc = (f&15)*4;
                        *(float4*)&ws[kk][cc] = *(const float4*)&Wn[(kt+kk)*DSZ + col0 + cc];
                    }
                    __syncthreads();
                    #pragma unroll
                    for (int kk = 0; kk < 32; kk++) {
                        float a = xs[r][kt+kk];
                        float4 w0 = *(float4*)&ws[kk][c4];
                        qacc[0] += a*w0.x; qacc[1] += a*w0.y; qacc[2] += a*w0.z; qacc[3] += a*w0.w;
                    }
                    __syncthreads();
                }
                int i = row0 + r;
                float* outp = (mat==0 ? g_q : (mat==1 ? g_k : g_v));
                int cg = col0 + c4;
                if (mat < 2) {
                    #pragma unroll
                    for (int p = 0; p < 2; p++) {
                        int c = cg + 2*p;
                        int jj = (c & 15) >> 1;
                        float inv = __powf(10000.0f, -(float)jj * 0.125f);
                        float ang = (float)i * inv;
                        float sn_, cs_;
                        __sincosf(ang, &sn_, &cs_);
                        float x0 = qacc[2*p], x1 = qacc[2*p+1];
                        qacc[2*p]   = x0*cs_ - x1*sn_;
                        qacc[2*p+1] = x0*sn_ + x1*cs_;
                    }
                }
                #pragma unroll
                for (int j = 0; j < 4; j++) outp[i*DSZ + cg + j] = qacc[j];
            } else if (u == 0) {
                // finalnorm + unit-normalize, write transposed
                float (*ps)[16] = (float(*)[16])(smem_f + 11776);
                float *rs       = smem_f + 12032;
                {
                    int rr = t>>4, ii = t&15;
                    float sum = 0.0f;
                    #pragma unroll
                    for (int j = 0; j < 8; j++) { float vv = xs[rr][ii*8+j]; sum += vv*vv; }
                    ps[rr][ii] = sum;
                }
                __syncthreads();
                if (t < 16) {
                    float sum = 0.0f;
                    #pragma unroll
                    for (int i2 = 0; i2 < 16; i2++) sum += ps[t][i2];
                    rs[t] = rsqrtf(sum * (1.0f/128.0f) + EPSV);
                }
                __syncthreads();
                {
                    int rr = t>>4, ii = t&15;
                    float sc = rs[rr];
                    float sum2 = 0.0f;
                    #pragma unroll
                    for (int j = 0; j < 8; j++) {
                        int c = ii*8+j;
                        float tv = xs[rr][c]*sc*fw[c];
                        xs[rr][c] = tv;
                        sum2 += tv*tv;
                    }
                    ps[rr][ii] = sum2;
                }
                __syncthreads();
                if (t < 16) {
                    float sum = 0.0f;
                    #pragma unroll
                    for (int i2 = 0; i2 < 16; i2++) sum += ps[t][i2];
                    rs[t] = rsqrtf(sum);
                }
                __syncthreads();
                {
                    int rr = t>>4, ii = t&15;
                    float sc = rs[rr];
                    int row = row0 + rr;
                    #pragma unroll
                    for (int j = 0; j < 8; j++) {
                        int c = ii*8+j;
                        g_xnT[c*SQ + row] = xs[rr][c]*sc;
                    }
                }
            }
        }
        if (layer < NL-1) grid_sync();   // barrier 3
    }
}

// =====================================================================
// logits: self-contained (computes binv/bsum per v-tile from w_raw).
// grid (128 v-tiles x 4 s-tiles), 256 threads, thread tile 2s x 4v.
// =====================================================================
__global__ __launch_bounds__(256) void logits_kernel(const float* __restrict__ w_raw,
                                                     float* __restrict__ out) {
    __shared__ float as_[16][32];
    __shared__ float bs[16][64];
    __shared__ float cs[16][64];
    __shared__ float sbinv[64], sbsum[64];
    __shared__ float pss[4][64], psq[4][64];
    int t = threadIdx.x;
    int v0 = blockIdx.x * 64;
    int s0 = blockIdx.y * 32;

    // prepass: per-tile column stats
    {
        int v = t & 63, part = t >> 6;
        float ss = 0.0f, sq = 0.0f;
        #pragma unroll 4
        for (int dd = 0; dd < 32; dd++) {
            float s = sigmoidf_(w_raw[(part*32 + dd)*VSZ + v0 + v]);
            ss += s; sq += s*s;
        }
        pss[part][v] = ss; psq[part][v] = sq;
    }
    __syncthreads();
    if (t < 64) {
        float ss = pss[0][t] + pss[1][t] + pss[2][t] + pss[3][t];
        float sq = psq[0][t] + psq[1][t] + psq[2][t] + psq[3][t];
        float inv = rsqrtf(sq);
        sbinv[t] = inv;
        sbsum[t] = ss * inv;
    }
    __syncthreads();

    int sgrp = t >> 4, vgrp = t & 15;
    float acc[2][4];
    #pragma unroll
    for (int i = 0; i < 2; i++)
        #pragma unroll
        for (int j = 0; j < 4; j++) acc[i][j] = 0.0f;

    #pragma unroll 1
    for (int d0 = 0; d0 < 128; d0 += 16) {
        for (int e = t; e < 512; e += 256)
            as_[e>>5][e&31] = g_xnT[(d0 + (e>>5))*SQ + s0 + (e&31)];
        for (int e = t; e < 1024; e += 256) {
            int dd = e>>6, vv = e&63;
            float b = sigmoidf_(w_raw[(d0+dd)*VSZ + v0 + vv]) * sbinv[vv];
            bs[dd][vv] = b;
            cs[dd][vv] = 1.0f - b;
        }
        __syncthreads();
        #pragma unroll
        for (int dd = 0; dd < 16; dd++) {
            float2 av = *(float2*)&as_[dd][sgrp*2];
            float4 bv = *(float4*)&bs[dd][vgrp*4];
            float4 cv = *(float4*)&cs[dd][vgrp*4];
            float aa[2] = {av.x, av.y};
            float bb[4] = {bv.x, bv.y, bv.z, bv.w};
            float cc[4] = {cv.x, cv.y, cv.z, cv.w};
            #pragma unroll
            for (int i = 0; i < 2; i++)
                #pragma unroll
                for (int j = 0; j < 4; j++)
                    if (aa[i] <= bb[j]) acc[i][j] += cc[j];
        }
        __syncthreads();
    }
    float bsum[4] = {sbsum[vgrp*4], sbsum[vgrp*4+1], sbsum[vgrp*4+2], sbsum[vgrp*4+3]};
    #pragma unroll
    for (int i = 0; i < 2; i++) {
        int s = s0 + sgrp*2 + i;
        float4 res;
        float* rp = (float*)&res;
        #pragma unroll
        for (int j = 0; j < 4; j++) {
            float val = (acc[i][j] + bsum[j]) * (1.0f/128.0f);
            rp[j] = fminf(fmaxf(val, 1e-6f), 1.0f - 1e-6f);
        }
        *(float4*)&out[s*VSZ + v0 + vgrp*4] = res;
    }
}

extern "C" void kernel_launch(void* const* d_in, const int* in_sizes, int n_in,
                              void* d_out, int out_size) {
    (void)in_sizes; (void)n_in; (void)out_size;
    const int*   idx   = (const int*)  d_in[0];
    const float* w_raw = (const float*)d_in[1];
    const float* n1w   = (const float*)d_in[2];
    const float* n2w   = (const float*)d_in[3];
    const float* wq    = (const float*)d_in[4];
    const float* wk    = (const float*)d_in[5];
    const float* wv    = (const float*)d_in[6];
    const float* wo    = (const float*)d_in[7];
    const float* w1    = (const float*)d_in[8];
    const float* w3    = (const float*)d_in[9];
    const float* w2    = (const float*)d_in[10];
    const float* fw    = (const float*)d_in[11];
    float* out = (float*)d_out;

    fused_kernel<<<NBLK, 256>>>(idx, w_raw, n1w, n2w, wq, wk, wv, wo, w1, w3, w2, fw);
    logits_kernel<<<dim3(128, 4), 256>>>(w_raw, out);
}